// round 15
// baseline (speedup 1.0000x reference)
#include <cuda_runtime.h>
#include <cuda_fp16.h>
#include <cstdint>

// Problem dims (fixed)
#define Bc  4
#define Sc  2048
#define Ec  1024
#define Hc  16
#define Dc  64
#define HDc (Hc * Dc)      // 1024
#define Mc  (Bc * Sc)      // 8192

// Scratch (fp16 pipeline)
__device__ __half g_Qh[Bc * Hc * Sc * Dc];
__device__ __half g_Kh[Bc * Hc * Sc * Dc];
__device__ __half g_Vh[Bc * Hc * Sc * Dc];
__device__ __half g_AOh[Bc * Sc * HDc];
__device__ __half g_xh [Mc * Ec];
__device__ __half g_Wqt[Hc * Dc * Ec];   // transposed [h][d][e]
__device__ __half g_Wkt[Hc * Dc * Ec];
__device__ __half g_Wvt[Hc * Dc * Ec];
__device__ __half g_Wot[Ec * HDc];       // transposed [n][k]

// ---------------------------------------------------------------------------
// helpers
// ---------------------------------------------------------------------------
__device__ __forceinline__ unsigned pk(float a, float b) {
    __half2 h = __floats2half2_rn(a, b);
    return *reinterpret_cast<unsigned*>(&h);
}

__device__ __forceinline__ float ex2(float x) {
    float y;
    asm("ex2.approx.f32 %0, %1;" : "=f"(y) : "f"(x));
    return y;
}

__device__ __forceinline__ void mma16(float* d, const unsigned* a, unsigned b0, unsigned b1) {
    asm volatile(
        "mma.sync.aligned.m16n8k16.row.col.f32.f16.f16.f32 "
        "{%0,%1,%2,%3}, {%4,%5,%6,%7}, {%8,%9}, {%0,%1,%2,%3};"
        : "+f"(d[0]), "+f"(d[1]), "+f"(d[2]), "+f"(d[3])
        : "r"(a[0]), "r"(a[1]), "r"(a[2]), "r"(a[3]), "r"(b0), "r"(b1));
}

__device__ __forceinline__ void ldsm4(unsigned* f, unsigned addr_bytes) {
    asm volatile("ldmatrix.sync.aligned.m8n8.x4.shared.b16 {%0,%1,%2,%3}, [%4];"
        : "=r"(f[0]), "=r"(f[1]), "=r"(f[2]), "=r"(f[3]) : "r"(addr_bytes));
}
__device__ __forceinline__ void ldsm4t(unsigned* f, unsigned addr_bytes) {
    asm volatile("ldmatrix.sync.aligned.m8n8.x4.trans.shared.b16 {%0,%1,%2,%3}, [%4];"
        : "=r"(f[0]), "=r"(f[1]), "=r"(f[2]), "=r"(f[3]) : "r"(addr_bytes));
}

__device__ __forceinline__ void cp16(void* smem, const void* g) {
    unsigned sa = (unsigned)__cvta_generic_to_shared(smem);
    asm volatile("cp.async.cg.shared.global [%0], [%1], 16;" :: "r"(sa), "l"(g));
}
#define CP_COMMIT asm volatile("cp.async.commit_group;")
#define CP_WAIT0  asm volatile("cp.async.wait_group 0;")

// ---------------------------------------------------------------------------
// Prepass (ONE launch): blocks [0,3072) Wq/Wk/Wv transpose tiles,
// [3072,4096) Wo transpose tiles, [4096,4608) x fp32->fp16 grid-stride.
// ---------------------------------------------------------------------------
__global__ __launch_bounds__(256) void prepass_kernel(
    const float* __restrict__ x,
    const float* __restrict__ Wq, const float* __restrict__ Wk,
    const float* __restrict__ Wv, const float* __restrict__ Wo)
{
    __shared__ float t[32][33];
    const int blk = blockIdx.x;
    const int tx = threadIdx.x & 31, ty = threadIdx.x >> 5;

    if (blk < 3072) {
        // Wq/Wk/Wv [h][E][D] -> [h][D][E]
        const int xb = blk & 1, yb = (blk >> 1) & 31, z = blk >> 6;
        const int mat = z >> 4, h = z & 15;
        const float* S = ((mat == 0) ? Wq : (mat == 1) ? Wk : Wv) + (size_t)h * Ec * Dc;
        __half* D = ((mat == 0) ? g_Wqt : (mat == 1) ? g_Wkt : g_Wvt) + (size_t)h * Dc * Ec;
        int c0 = xb * 32, r0 = yb * 32;
#pragma unroll
        for (int i = 0; i < 32; i += 8)
            t[ty + i][tx] = S[(size_t)(r0 + ty + i) * Dc + c0 + tx];
        __syncthreads();
#pragma unroll
        for (int i = 0; i < 32; i += 8)
            D[(size_t)(c0 + ty + i) * Ec + r0 + tx] = __float2half_rn(t[tx][ty + i]);
    } else if (blk < 4096) {
        // Wo [HD][E] -> [E][HD]
        const int idx2 = blk - 3072;
        int c0 = (idx2 & 31) * 32, r0 = (idx2 >> 5) * 32;
#pragma unroll
        for (int i = 0; i < 32; i += 8)
            t[ty + i][tx] = Wo[(size_t)(r0 + ty + i) * Ec + c0 + tx];
        __syncthreads();
#pragma unroll
        for (int i = 0; i < 32; i += 8)
            g_Wot[(size_t)(c0 + ty + i) * HDc + r0 + tx] = __float2half_rn(t[tx][ty + i]);
    } else {
        // x fp32 -> fp16
        const float4* src = (const float4*)x;
        uint2* dst = (uint2*)g_xh;
        const int n4 = Mc * Ec / 4;
        for (int i = (blk - 4096) * 256 + threadIdx.x; i < n4; i += 512 * 256) {
            float4 v = src[i];
            dst[i] = make_uint2(pk(v.x, v.y), pk(v.z, v.w));
        }
    }
}

// ---------------------------------------------------------------------------
// Kernel 1: FUSED QKV projection (R14 config — at mma.sync roofline, frozen).
// Block 128(M) x 192(N) x 64(K halves). 256 thr = 8 warps (4m x 2n),
// warp tile 32x96. Rows 144 B. smem: A0@0 A1@18432 | B0@36864 B1@64512
// ---------------------------------------------------------------------------
#define QKV_A(b) ((b) * 18432)
#define QKV_B(b) (36864 + (b) * 27648)
#define QKV_SMEM 92160

__global__ __launch_bounds__(256, 1) void qkv_fp16_kernel(
    const float* __restrict__ bq, const float* __restrict__ bk,
    const float* __restrict__ bv)
{
    extern __shared__ __align__(16) char smq[];
    const unsigned sb = (unsigned)__cvta_generic_to_shared(smq);

    const int tid  = threadIdx.x;
    const int warp = tid >> 5, lane = tid & 31;
    const int wm = warp >> 1, wn = warp & 1;
    const int r = lane >> 2, c = lane & 3;
    const int ln15 = lane & 15, lhiB = (lane >> 4) * 16;
    const int m0 = blockIdx.x * 128;
    const int h  = blockIdx.y;

    const __half* __restrict__ W0 = g_Wqt + (size_t)h * Dc * Ec;
    const __half* __restrict__ W1 = g_Wkt + (size_t)h * Dc * Ec;
    const __half* __restrict__ W2 = g_Wvt + (size_t)h * Dc * Ec;
    const __half* __restrict__ xh = g_xh;

#pragma unroll
    for (int it = 0; it < 4; it++) {
        int i = tid + it * 256; int m = i >> 3; int ch = i & 7;
        cp16(smq + QKV_A(0) + m * 144 + ch * 16, xh + (size_t)(m0 + m) * Ec + ch * 8);
    }
#pragma unroll
    for (int it = 0; it < 6; it++) {
        int i = tid + it * 256; int row = i >> 3; int ch = i & 7;
        const __half* w = (row < 64) ? W0 : (row < 128) ? W1 : W2;
        cp16(smq + QKV_B(0) + row * 144 + ch * 16, w + (size_t)(row & 63) * Ec + ch * 8);
    }
    CP_COMMIT;

    float acc[2][12][4];
#pragma unroll
    for (int mt = 0; mt < 2; mt++)
#pragma unroll
        for (int nt = 0; nt < 12; nt++)
#pragma unroll
            for (int j = 0; j < 4; j++) acc[mt][nt][j] = 0.0f;

    const unsigned aOff = (unsigned)((wm * 32 + ln15) * 144) + lhiB;
    const unsigned bOff = (unsigned)((wn * 96 + ln15) * 144) + lhiB;

    int buf = 0;
    for (int k0 = 0; k0 < Ec; k0 += 64, buf ^= 1) {
        CP_WAIT0;
        __syncthreads();

        if (k0 + 64 < Ec) {
            int nb = buf ^ 1;
#pragma unroll
            for (int it = 0; it < 4; it++) {
                int i = tid + it * 256; int m = i >> 3; int ch = i & 7;
                cp16(smq + QKV_A(nb) + m * 144 + ch * 16,
                     xh + (size_t)(m0 + m) * Ec + k0 + 64 + ch * 8);
            }
#pragma unroll
            for (int it = 0; it < 6; it++) {
                int i = tid + it * 256; int row = i >> 3; int ch = i & 7;
                const __half* w = (row < 64) ? W0 : (row < 128) ? W1 : W2;
                cp16(smq + QKV_B(nb) + row * 144 + ch * 16,
                     w + (size_t)(row & 63) * Ec + k0 + 64 + ch * 8);
            }
            CP_COMMIT;
        }

        const unsigned aB = sb + QKV_A(buf) + aOff;
        const unsigned bB = sb + QKV_B(buf) + bOff;
#pragma unroll
        for (int kk = 0; kk < 4; kk++) {
            unsigned af[2][4], bf[6][4];
            ldsm4(af[0], aB + kk * 32);
            ldsm4(af[1], aB + 16 * 144 + kk * 32);
#pragma unroll
            for (int p = 0; p < 6; p++)
                ldsm4(bf[p], bB + p * 16 * 144 + kk * 32);
#pragma unroll
            for (int nt = 0; nt < 12; nt++) {
                unsigned b0 = bf[nt >> 1][nt & 1];
                unsigned b1 = bf[nt >> 1][2 + (nt & 1)];
#pragma unroll
                for (int mt = 0; mt < 2; mt++)
                    mma16(acc[mt][nt], af[mt], b0, b1);
            }
        }
    }

    const int bI = m0 >> 11;
    const int sBase = m0 & 2047;
#pragma unroll
    for (int nt = 0; nt < 12; nt++) {
        int g   = wn * 96 + nt * 8;
        int mat = g >> 6;
        int d   = (g & 63) + 2 * c;
        __half* Out = (mat == 0) ? g_Qh : (mat == 1) ? g_Kh : g_Vh;
        const float* bias = (mat == 0) ? bq : (mat == 1) ? bk : bv;
        float bb0 = bias[h * Dc + d], bb1 = bias[h * Dc + d + 1];
#pragma unroll
        for (int mt = 0; mt < 2; mt++) {
            int lr = wm * 32 + mt * 16 + r;
            size_t base = ((((size_t)bI * Hc + h) * Sc) + sBase + lr) * Dc + d;
            *(unsigned*)(Out + base)          = pk(acc[mt][nt][0] + bb0, acc[mt][nt][1] + bb1);
            *(unsigned*)(Out + base + 8 * Dc) = pk(acc[mt][nt][2] + bb0, acc[mt][nt][3] + bb1);
        }
    }
}

// ---------------------------------------------------------------------------
// Kernel 3: output projection, occ 2 (R14 config, frozen).
// ---------------------------------------------------------------------------
#define O_A(b) ((b) * 10240)
#define O_B(b) (20480 + (b) * 10240)
#define O_SMEM 40960

__global__ __launch_bounds__(256, 2) void out_fp16_kernel(
    const float* __restrict__ bo, float* __restrict__ outp)
{
    extern __shared__ __align__(16) char smo[];
    const unsigned sb = (unsigned)__cvta_generic_to_shared(smo);

    const __half* __restrict__ A = (const __half*)g_AOh;
    const __half* __restrict__ B = (const __half*)g_Wot;

    const int tid  = threadIdx.x;
    const int warp = tid >> 5, lane = tid & 31;
    const int wm = warp >> 1, wn = warp & 1;
    const int r = lane >> 2, c = lane & 3;
    const int ln15 = lane & 15, lhiB = (lane >> 4) * 16;
    const int m0 = blockIdx.y * 128;
    const int ncol0 = blockIdx.x * 128;

#pragma unroll
    for (int it = 0; it < 2; it++) {
        int i = tid + it * 256; int m = i >> 2; int ch = i & 3;
        cp16(smo + O_A(0) + m * 80 + ch * 16, A + (size_t)(m0 + m) * HDc + ch * 8);
    }
#pragma unroll
    for (int it = 0; it < 2; it++) {
        int i = tid + it * 256; int row = i >> 2; int ch = i & 3;
        cp16(smo + O_B(0) + row * 80 + ch * 16,
             B + (size_t)(ncol0 + row) * HDc + ch * 8);
    }
    CP_COMMIT;

    float acc[2][8][4];
#pragma unroll
    for (int mt = 0; mt < 2; mt++)
#pragma unroll
        for (int nt = 0; nt < 8; nt++)
#pragma unroll
            for (int j = 0; j < 4; j++) acc[mt][nt][j] = 0.0f;

    const unsigned aOff = (unsigned)((wm * 32 + ln15) * 80) + lhiB;
    const unsigned bOff = (unsigned)((wn * 64 + ln15) * 80) + lhiB;

    int buf = 0;
    for (int k0 = 0; k0 < HDc; k0 += 32, buf ^= 1) {
        CP_WAIT0;
        __syncthreads();

        if (k0 + 32 < HDc) {
            int nb = buf ^ 1;
#pragma unroll
            for (int it = 0; it < 2; it++) {
                int i = tid + it * 256; int m = i >> 2; int ch = i & 3;
                cp16(smo + O_A(nb) + m * 80 + ch * 16,
                     A + (size_t)(m0 + m) * HDc + k0 + 32 + ch * 8);
            }
#pragma unroll
            for (int it = 0; it < 2; it++) {
                int i = tid + it * 256; int row = i >> 2; int ch = i & 3;
                cp16(smo + O_B(nb) + row * 80 + ch * 16,
                     B + (size_t)(ncol0 + row) * HDc + k0 + 32 + ch * 8);
            }
            CP_COMMIT;
        }

        const unsigned aB = sb + O_A(buf) + aOff;
        const unsigned bB = sb + O_B(buf) + bOff;
#pragma unroll
        for (int kk = 0; kk < 2; kk++) {
            unsigned af[2][4], bf[4][4];
            ldsm4(af[0], aB + kk * 32);
            ldsm4(af[1], aB + 16 * 80 + kk * 32);
#pragma unroll
            for (int p = 0; p < 4; p++)
                ldsm4(bf[p], bB + p * 16 * 80 + kk * 32);
#pragma unroll
            for (int nt = 0; nt < 8; nt++) {
                unsigned b0 = bf[nt >> 1][nt & 1];
                unsigned b1 = bf[nt >> 1][2 + (nt & 1)];
#pragma unroll
                for (int mt = 0; mt < 2; mt++)
                    mma16(acc[mt][nt], af[mt], b0, b1);
            }
        }
    }

#pragma unroll
    for (int mt = 0; mt < 2; mt++) {
        int mrow = m0 + wm * 32 + mt * 16 + r;
#pragma unroll
        for (int nt = 0; nt < 8; nt++) {
            int d = ncol0 + wn * 64 + nt * 8 + 2 * c;
            float bb0 = bo[d], bb1 = bo[d + 1];
            *(float2*)(outp + (size_t)mrow * Ec + d) =
                make_float2(acc[mt][nt][0] + bb0, acc[mt][nt][1] + bb1);
            *(float2*)(outp + (size_t)(mrow + 8) * Ec + d) =
                make_float2(acc[mt][nt][2] + bb0, acc[mt][nt][3] + bb1);
        }
    }
}

// ---------------------------------------------------------------------------
// Kernel 2: flash attention, BQ=256 (512 thr = 16 warps, occ 1 — same 16
// warps/SM as before but HALF the iterations and HALF the staging issue).
// R14 softmax (exp2 domain, diagonal-only masking, deferred l-reduction).
// smem: K0@0 V0@9216 | K1@18432 V1@27648 -> 36864 B (Q staged across all).
// ---------------------------------------------------------------------------
#define F_SMEM 36864
#define SCL 0.18033688011112042f   // 0.125 * log2(e)

__device__ __forceinline__ void stage_kv_h(char* s, int base,
                                           const __half* Kb, const __half* Vb,
                                           int k0, int tid)
{
    // 512 threads: exactly one K chunk and one V chunk per thread
    int row = tid >> 3, ch = tid & 7;
    cp16(s + base + row * 144 + ch * 16,        Kb + (size_t)(k0 + row) * Dc + ch * 8);
    cp16(s + base + 9216 + row * 144 + ch * 16, Vb + (size_t)(k0 + row) * Dc + ch * 8);
}

__global__ __launch_bounds__(512, 1) void flash_fp16_kernel()
{
    extern __shared__ __align__(16) char smf[];
    const unsigned sb = (unsigned)__cvta_generic_to_shared(smf);

    const int bh = blockIdx.y;
    const int b  = bh >> 4, h = bh & 15;
    const int bx = gridDim.x - 1 - blockIdx.x;     // heavy tiles first
    const int q0 = bx * 256;

    const __half* __restrict__ Qb = g_Qh + (size_t)bh * Sc * Dc;
    const __half* __restrict__ Kb = g_Kh + (size_t)bh * Sc * Dc;
    const __half* __restrict__ Vb = g_Vh + (size_t)bh * Sc * Dc;

    const int tid  = threadIdx.x;
    const int warp = tid >> 5, lane = tid & 31;
    const int r = lane >> 2, c = lane & 3;
    const int ln15 = lane & 15, lhiB = (lane >> 4) * 16;

    // stage Q (256x64 halves = 36864 B, fills whole smem), extract, then free
#pragma unroll
    for (int it = 0; it < 4; it++) {
        int i = tid + it * 512;
        int row = i >> 3, ch = i & 7;
        cp16(smf + row * 144 + ch * 16, Qb + (size_t)(q0 + row) * Dc + ch * 8);
    }
    CP_COMMIT; CP_WAIT0;
    __syncthreads();

    unsigned qf[4][4];
    {
        const unsigned qB = sb + (unsigned)((warp * 16 + ln15) * 144) + lhiB;
#pragma unroll
        for (int kk = 0; kk < 4; kk++)
            ldsm4(qf[kk], qB + kk * 32);
    }
    __syncthreads();

    const int nkt = 4 * (bx + 1);
    stage_kv_h(smf, 0, Kb, Vb, 0, tid);
    CP_COMMIT;

    float of[8][4];
#pragma unroll
    for (int nt = 0; nt < 8; nt++)
#pragma unroll
        for (int j = 0; j < 4; j++) of[nt][j] = 0.0f;
    float m_lo = -1e30f, m_hi = -1e30f, l_lo = 0.0f, l_hi = 0.0f;

    const int qwmin = q0 + warp * 16;
    const int qlo = qwmin + r;
    const int qhi = qlo + 8;
    const int qmax = qwmin + 15;

    const int lm = lane >> 3, lr8 = lane & 7;

    int buf = 0;
    for (int kt = 0; kt < nkt; kt++) {
        CP_WAIT0;
        __syncthreads();
        if (kt + 1 < nkt) {
            stage_kv_h(smf, (buf ^ 1) * 18432, Kb, Vb, (kt + 1) * 64, tid);
            CP_COMMIT;
        }
        const int kbase = kt * 64;
        if (kbase <= qmax) {
            const unsigned kB = sb + buf * 18432 + (unsigned)(ln15 * 144) + lhiB;
            const unsigned vbase = sb + buf * 18432 + 9216;

            // S = Q K^T
            float sf[8][4];
#pragma unroll
            for (int nt = 0; nt < 8; nt++)
                sf[nt][0] = sf[nt][1] = sf[nt][2] = sf[nt][3] = 0.0f;
#pragma unroll
            for (int kk = 0; kk < 4; kk++) {
                unsigned kf[4][4];
#pragma unroll
                for (int p = 0; p < 4; p++)
                    ldsm4(kf[p], kB + p * 16 * 144 + kk * 32);
#pragma unroll
                for (int nt = 0; nt < 8; nt++)
                    mma16(sf[nt], qf[kk], kf[nt >> 1][nt & 1], kf[nt >> 1][2 + (nt & 1)]);
            }

            // scale (log2 domain); mask only diagonal tiles (warp-uniform)
            float mx_lo = -1e30f, mx_hi = -1e30f;
            if (kbase + 63 > qwmin) {
#pragma unroll
                for (int nt = 0; nt < 8; nt++) {
                    int kg0 = kbase + nt * 8 + 2 * c;
                    int kg1 = kg0 + 1;
                    float s0 = sf[nt][0] * SCL; if (kg0 > qlo) s0 = -1e30f;
                    float s1 = sf[nt][1] * SCL; if (kg1 > qlo) s1 = -1e30f;
                    float s2 = sf[nt][2] * SCL; if (kg0 > qhi) s2 = -1e30f;
                    float s3 = sf[nt][3] * SCL; if (kg1 > qhi) s3 = -1e30f;
                    sf[nt][0] = s0; sf[nt][1] = s1; sf[nt][2] = s2; sf[nt][3] = s3;
                    mx_lo = fmaxf(mx_lo, fmaxf(s0, s1));
                    mx_hi = fmaxf(mx_hi, fmaxf(s2, s3));
                }
            } else {
#pragma unroll
                for (int nt = 0; nt < 8; nt++) {
                    float s0 = sf[nt][0] * SCL;
                    float s1 = sf[nt][1] * SCL;
                    float s2 = sf[nt][2] * SCL;
                    float s3 = sf[nt][3] * SCL;
                    sf[nt][0] = s0; sf[nt][1] = s1; sf[nt][2] = s2; sf[nt][3] = s3;
                    mx_lo = fmaxf(mx_lo, fmaxf(s0, s1));
                    mx_hi = fmaxf(mx_hi, fmaxf(s2, s3));
                }
            }
            mx_lo = fmaxf(mx_lo, __shfl_xor_sync(0xffffffffu, mx_lo, 1));
            mx_lo = fmaxf(mx_lo, __shfl_xor_sync(0xffffffffu, mx_lo, 2));
            mx_hi = fmaxf(mx_hi, __shfl_xor_sync(0xffffffffu, mx_hi, 1));
            mx_hi = fmaxf(mx_hi, __shfl_xor_sync(0xffffffffu, mx_hi, 2));

            float mn_lo = fmaxf(m_lo, mx_lo), mn_hi = fmaxf(m_hi, mx_hi);
            float a_lo = ex2(m_lo - mn_lo), a_hi = ex2(m_hi - mn_hi);

            unsigned pr0[8], pr1[8];
            float ps_lo = 0.0f, ps_hi = 0.0f;
#pragma unroll
            for (int nt = 0; nt < 8; nt++) {
                float p0 = ex2(sf[nt][0] - mn_lo);
                float p1 = ex2(sf[nt][1] - mn_lo);
                float p2 = ex2(sf[nt][2] - mn_hi);
                float p3 = ex2(sf[nt][3] - mn_hi);
                ps_lo += p0 + p1;  ps_hi += p2 + p3;
                pr0[nt] = pk(p0, p1);
                pr1[nt] = pk(p2, p3);
            }
            l_lo = l_lo * a_lo + ps_lo;
            l_hi = l_hi * a_hi + ps_hi;
            m_lo = mn_lo; m_hi = mn_hi;

#pragma unroll
            for (int nt = 0; nt < 8; nt++) {
                of[nt][0] *= a_lo; of[nt][1] *= a_lo;
                of[nt][2] *= a_hi; of[nt][3] *= a_hi;
            }

            // O += P V
#pragma unroll
            for (int kk = 0; kk < 4; kk++) {
                unsigned pa[4] = { pr0[2 * kk], pr1[2 * kk],
                                   pr0[2 * kk + 1], pr1[2 * kk + 1] };
#pragma unroll
                for (int ntp = 0; ntp < 4; ntp++) {
                    unsigned vf[4];
                    unsigned va = vbase
                        + (unsigned)((kk * 16 + (lm & 1) * 8 + lr8) * 144)
                        + (unsigned)((ntp * 16 + (lm >> 1) * 8) * 2);
                    ldsm4t(vf, va);
                    mma16(of[2 * ntp],     pa, vf[0], vf[1]);
                    mma16(of[2 * ntp + 1], pa, vf[2], vf[3]);
                }
            }
        }
        buf ^= 1;
    }

    // final l reduction across the quad
    l_lo += __shfl_xor_sync(0xffffffffu, l_lo, 1);
    l_lo += __shfl_xor_sync(0xffffffffu, l_lo, 2);
    l_hi += __shfl_xor_sync(0xffffffffu, l_hi, 1);
    l_hi += __shfl_xor_sync(0xffffffffu, l_hi, 2);

    float il_lo = 1.0f / l_lo, il_hi = 1.0f / l_hi;
    size_t rb_lo = ((size_t)b * Sc + qlo) * HDc + h * Dc;
    size_t rb_hi = ((size_t)b * Sc + qhi) * HDc + h * Dc;
#pragma unroll
    for (int nt = 0; nt < 8; nt++) {
        int d = nt * 8 + 2 * c;
        *(unsigned*)(g_AOh + rb_lo + d) = pk(of[nt][0] * il_lo, of[nt][1] * il_lo);
        *(unsigned*)(g_AOh + rb_hi + d) = pk(of[nt][2] * il_hi, of[nt][3] * il_hi);
    }
}

// ---------------------------------------------------------------------------
extern "C" void kernel_launch(void* const* d_in, const int* in_sizes, int n_in,
                              void* d_out, int out_size)
{
    const float* x  = (const float*)d_in[0];
    const float* Wq = (const float*)d_in[1];
    const float* bq = (const float*)d_in[2];
    const float* Wk = (const float*)d_in[3];
    const float* bk = (const float*)d_in[4];
    const float* Wv = (const float*)d_in[5];
    const float* bv = (const float*)d_in[6];
    const float* Wo = (const float*)d_in[7];
    const float* bo = (const float*)d_in[8];
    float* out = (float*)d_out;

    cudaFuncSetAttribute(qkv_fp16_kernel,
                         cudaFuncAttributeMaxDynamicSharedMemorySize, QKV_SMEM);
    cudaFuncSetAttribute(flash_fp16_kernel,
                         cudaFuncAttributeMaxDynamicSharedMemorySize, F_SMEM);
    cudaFuncSetAttribute(out_fp16_kernel,
                         cudaFuncAttributeMaxDynamicSharedMemorySize, O_SMEM);

    prepass_kernel<<<4608, 256>>>(x, Wq, Wk, Wv, Wo);

    dim3 g1(Mc / 128, Hc);
    qkv_fp16_kernel<<<g1, 256, QKV_SMEM>>>(bq, bk, bv);

    dim3 g2(Sc / 256, Bc * Hc);
    flash_fp16_kernel<<<g2, 512, F_SMEM>>>();

    dim3 g3(Ec / 128, Mc / 128);
    out_fp16_kernel<<<g3, 256, O_SMEM>>>(bo, out);
}

// round 16
// speedup vs baseline: 1.0395x; 1.0395x over previous
#include <cuda_runtime.h>
#include <cuda_fp16.h>
#include <cstdint>

// Problem dims (fixed)
#define Bc  4
#define Sc  2048
#define Ec  1024
#define Hc  16
#define Dc  64
#define HDc (Hc * Dc)      // 1024
#define Mc  (Bc * Sc)      // 8192

// Scratch (fp16 pipeline)
__device__ __half g_Qh[Bc * Hc * Sc * Dc];
__device__ __half g_Kh[Bc * Hc * Sc * Dc];
__device__ __half g_Vh[Bc * Hc * Sc * Dc];
__device__ __half g_AOh[Bc * Sc * HDc];
__device__ __half g_xh [Mc * Ec];
__device__ __half g_Wqt[Hc * Dc * Ec];   // transposed [h][d][e]
__device__ __half g_Wkt[Hc * Dc * Ec];
__device__ __half g_Wvt[Hc * Dc * Ec];
__device__ __half g_Wot[Ec * HDc];       // transposed [n][k]

// ---------------------------------------------------------------------------
// helpers
// ---------------------------------------------------------------------------
__device__ __forceinline__ unsigned pk(float a, float b) {
    __half2 h = __floats2half2_rn(a, b);
    return *reinterpret_cast<unsigned*>(&h);
}

__device__ __forceinline__ float ex2(float x) {
    float y;
    asm("ex2.approx.f32 %0, %1;" : "=f"(y) : "f"(x));
    return y;
}

__device__ __forceinline__ void mma16(float* d, const unsigned* a, unsigned b0, unsigned b1) {
    asm volatile(
        "mma.sync.aligned.m16n8k16.row.col.f32.f16.f16.f32 "
        "{%0,%1,%2,%3}, {%4,%5,%6,%7}, {%8,%9}, {%0,%1,%2,%3};"
        : "+f"(d[0]), "+f"(d[1]), "+f"(d[2]), "+f"(d[3])
        : "r"(a[0]), "r"(a[1]), "r"(a[2]), "r"(a[3]), "r"(b0), "r"(b1));
}

__device__ __forceinline__ void ldsm4(unsigned* f, unsigned addr_bytes) {
    asm volatile("ldmatrix.sync.aligned.m8n8.x4.shared.b16 {%0,%1,%2,%3}, [%4];"
        : "=r"(f[0]), "=r"(f[1]), "=r"(f[2]), "=r"(f[3]) : "r"(addr_bytes));
}
__device__ __forceinline__ void ldsm4t(unsigned* f, unsigned addr_bytes) {
    asm volatile("ldmatrix.sync.aligned.m8n8.x4.trans.shared.b16 {%0,%1,%2,%3}, [%4];"
        : "=r"(f[0]), "=r"(f[1]), "=r"(f[2]), "=r"(f[3]) : "r"(addr_bytes));
}

__device__ __forceinline__ void cp16(void* smem, const void* g) {
    unsigned sa = (unsigned)__cvta_generic_to_shared(smem);
    asm volatile("cp.async.cg.shared.global [%0], [%1], 16;" :: "r"(sa), "l"(g));
}
#define CP_COMMIT asm volatile("cp.async.commit_group;")
#define CP_WAIT0  asm volatile("cp.async.wait_group 0;")

// ---------------------------------------------------------------------------
// Prepass (ONE launch, R15): blocks [0,3072) Wq/Wk/Wv transpose,
// [3072,4096) Wo transpose, [4096,4608) x fp32->fp16 grid-stride.
// ---------------------------------------------------------------------------
__global__ __launch_bounds__(256) void prepass_kernel(
    const float* __restrict__ x,
    const float* __restrict__ Wq, const float* __restrict__ Wk,
    const float* __restrict__ Wv, const float* __restrict__ Wo)
{
    __shared__ float t[32][33];
    const int blk = blockIdx.x;
    const int tx = threadIdx.x & 31, ty = threadIdx.x >> 5;

    if (blk < 3072) {
        const int xb = blk & 1, yb = (blk >> 1) & 31, z = blk >> 6;
        const int mat = z >> 4, h = z & 15;
        const float* S = ((mat == 0) ? Wq : (mat == 1) ? Wk : Wv) + (size_t)h * Ec * Dc;
        __half* D = ((mat == 0) ? g_Wqt : (mat == 1) ? g_Wkt : g_Wvt) + (size_t)h * Dc * Ec;
        int c0 = xb * 32, r0 = yb * 32;
#pragma unroll
        for (int i = 0; i < 32; i += 8)
            t[ty + i][tx] = S[(size_t)(r0 + ty + i) * Dc + c0 + tx];
        __syncthreads();
#pragma unroll
        for (int i = 0; i < 32; i += 8)
            D[(size_t)(c0 + ty + i) * Ec + r0 + tx] = __float2half_rn(t[tx][ty + i]);
    } else if (blk < 4096) {
        const int idx2 = blk - 3072;
        int c0 = (idx2 & 31) * 32, r0 = (idx2 >> 5) * 32;
#pragma unroll
        for (int i = 0; i < 32; i += 8)
            t[ty + i][tx] = Wo[(size_t)(r0 + ty + i) * Ec + c0 + tx];
        __syncthreads();
#pragma unroll
        for (int i = 0; i < 32; i += 8)
            g_Wot[(size_t)(c0 + ty + i) * HDc + r0 + tx] = __float2half_rn(t[tx][ty + i]);
    } else {
        const float4* src = (const float4*)x;
        uint2* dst = (uint2*)g_xh;
        const int n4 = Mc * Ec / 4;
        for (int i = (blk - 4096) * 256 + threadIdx.x; i < n4; i += 512 * 256) {
            float4 v = src[i];
            dst[i] = make_uint2(pk(v.x, v.y), pk(v.z, v.w));
        }
    }
}

// ---------------------------------------------------------------------------
// Kernel 1: FUSED QKV projection (R14 config — at mma.sync roofline, frozen).
// Block 128(M) x 192(N) x 64(K halves). 256 thr = 8 warps (4m x 2n),
// warp tile 32x96. Rows 144 B. smem: A0@0 A1@18432 | B0@36864 B1@64512
// ---------------------------------------------------------------------------
#define QKV_A(b) ((b) * 18432)
#define QKV_B(b) (36864 + (b) * 27648)
#define QKV_SMEM 92160

__global__ __launch_bounds__(256, 1) void qkv_fp16_kernel(
    const float* __restrict__ bq, const float* __restrict__ bk,
    const float* __restrict__ bv)
{
    extern __shared__ __align__(16) char smq[];
    const unsigned sb = (unsigned)__cvta_generic_to_shared(smq);

    const int tid  = threadIdx.x;
    const int warp = tid >> 5, lane = tid & 31;
    const int wm = warp >> 1, wn = warp & 1;
    const int r = lane >> 2, c = lane & 3;
    const int ln15 = lane & 15, lhiB = (lane >> 4) * 16;
    const int m0 = blockIdx.x * 128;
    const int h  = blockIdx.y;

    const __half* __restrict__ W0 = g_Wqt + (size_t)h * Dc * Ec;
    const __half* __restrict__ W1 = g_Wkt + (size_t)h * Dc * Ec;
    const __half* __restrict__ W2 = g_Wvt + (size_t)h * Dc * Ec;
    const __half* __restrict__ xh = g_xh;

#pragma unroll
    for (int it = 0; it < 4; it++) {
        int i = tid + it * 256; int m = i >> 3; int ch = i & 7;
        cp16(smq + QKV_A(0) + m * 144 + ch * 16, xh + (size_t)(m0 + m) * Ec + ch * 8);
    }
#pragma unroll
    for (int it = 0; it < 6; it++) {
        int i = tid + it * 256; int row = i >> 3; int ch = i & 7;
        const __half* w = (row < 64) ? W0 : (row < 128) ? W1 : W2;
        cp16(smq + QKV_B(0) + row * 144 + ch * 16, w + (size_t)(row & 63) * Ec + ch * 8);
    }
    CP_COMMIT;

    float acc[2][12][4];
#pragma unroll
    for (int mt = 0; mt < 2; mt++)
#pragma unroll
        for (int nt = 0; nt < 12; nt++)
#pragma unroll
            for (int j = 0; j < 4; j++) acc[mt][nt][j] = 0.0f;

    const unsigned aOff = (unsigned)((wm * 32 + ln15) * 144) + lhiB;
    const unsigned bOff = (unsigned)((wn * 96 + ln15) * 144) + lhiB;

    int buf = 0;
    for (int k0 = 0; k0 < Ec; k0 += 64, buf ^= 1) {
        CP_WAIT0;
        __syncthreads();

        if (k0 + 64 < Ec) {
            int nb = buf ^ 1;
#pragma unroll
            for (int it = 0; it < 4; it++) {
                int i = tid + it * 256; int m = i >> 3; int ch = i & 7;
                cp16(smq + QKV_A(nb) + m * 144 + ch * 16,
                     xh + (size_t)(m0 + m) * Ec + k0 + 64 + ch * 8);
            }
#pragma unroll
            for (int it = 0; it < 6; it++) {
                int i = tid + it * 256; int row = i >> 3; int ch = i & 7;
                const __half* w = (row < 64) ? W0 : (row < 128) ? W1 : W2;
                cp16(smq + QKV_B(nb) + row * 144 + ch * 16,
                     w + (size_t)(row & 63) * Ec + k0 + 64 + ch * 8);
            }
            CP_COMMIT;
        }

        const unsigned aB = sb + QKV_A(buf) + aOff;
        const unsigned bB = sb + QKV_B(buf) + bOff;
#pragma unroll
        for (int kk = 0; kk < 4; kk++) {
            unsigned af[2][4], bf[6][4];
            ldsm4(af[0], aB + kk * 32);
            ldsm4(af[1], aB + 16 * 144 + kk * 32);
#pragma unroll
            for (int p = 0; p < 6; p++)
                ldsm4(bf[p], bB + p * 16 * 144 + kk * 32);
#pragma unroll
            for (int nt = 0; nt < 12; nt++) {
                unsigned b0 = bf[nt >> 1][nt & 1];
                unsigned b1 = bf[nt >> 1][2 + (nt & 1)];
#pragma unroll
                for (int mt = 0; mt < 2; mt++)
                    mma16(acc[mt][nt], af[mt], b0, b1);
            }
        }
    }

    const int bI = m0 >> 11;
    const int sBase = m0 & 2047;
#pragma unroll
    for (int nt = 0; nt < 12; nt++) {
        int g   = wn * 96 + nt * 8;
        int mat = g >> 6;
        int d   = (g & 63) + 2 * c;
        __half* Out = (mat == 0) ? g_Qh : (mat == 1) ? g_Kh : g_Vh;
        const float* bias = (mat == 0) ? bq : (mat == 1) ? bk : bv;
        float bb0 = bias[h * Dc + d], bb1 = bias[h * Dc + d + 1];
#pragma unroll
        for (int mt = 0; mt < 2; mt++) {
            int lr = wm * 32 + mt * 16 + r;
            size_t base = ((((size_t)bI * Hc + h) * Sc) + sBase + lr) * Dc + d;
            *(unsigned*)(Out + base)          = pk(acc[mt][nt][0] + bb0, acc[mt][nt][1] + bb1);
            *(unsigned*)(Out + base + 8 * Dc) = pk(acc[mt][nt][2] + bb0, acc[mt][nt][3] + bb1);
        }
    }
}

// ---------------------------------------------------------------------------
// Kernel 3: output projection. Block 128x128 x 64(K halves), OCC 2.
// 8 warps (4m x 2n), warp tile 32x64. Rows 144 B (R11 geometry, proven
// regs ~96 <= 128). Halved iteration count (16) + cross-CTA overlap.
// smem: A0@0 A1@18432 | B0@36864 B1@55296 -> 73728 B; 2 CTAs = 147456 B.
// ---------------------------------------------------------------------------
#define O_A(b) ((b) * 18432)
#define O_B(b) (36864 + (b) * 18432)
#define O_SMEM 73728

__global__ __launch_bounds__(256, 2) void out_fp16_kernel(
    const float* __restrict__ bo, float* __restrict__ outp)
{
    extern __shared__ __align__(16) char smo[];
    const unsigned sb = (unsigned)__cvta_generic_to_shared(smo);

    const __half* __restrict__ A = (const __half*)g_AOh;
    const __half* __restrict__ B = (const __half*)g_Wot;

    const int tid  = threadIdx.x;
    const int warp = tid >> 5, lane = tid & 31;
    const int wm = warp >> 1, wn = warp & 1;
    const int r = lane >> 2, c = lane & 3;
    const int ln15 = lane & 15, lhiB = (lane >> 4) * 16;
    const int m0 = blockIdx.y * 128;
    const int ncol0 = blockIdx.x * 128;

#pragma unroll
    for (int it = 0; it < 4; it++) {
        int i = tid + it * 256; int m = i >> 3; int ch = i & 7;
        cp16(smo + O_A(0) + m * 144 + ch * 16, A + (size_t)(m0 + m) * HDc + ch * 8);
    }
#pragma unroll
    for (int it = 0; it < 4; it++) {
        int i = tid + it * 256; int row = i >> 3; int ch = i & 7;
        cp16(smo + O_B(0) + row * 144 + ch * 16,
             B + (size_t)(ncol0 + row) * HDc + ch * 8);
    }
    CP_COMMIT;

    float acc[2][8][4];
#pragma unroll
    for (int mt = 0; mt < 2; mt++)
#pragma unroll
        for (int nt = 0; nt < 8; nt++)
#pragma unroll
            for (int j = 0; j < 4; j++) acc[mt][nt][j] = 0.0f;

    const unsigned aOff = (unsigned)((wm * 32 + ln15) * 144) + lhiB;
    const unsigned bOff = (unsigned)((wn * 64 + ln15) * 144) + lhiB;

    int buf = 0;
    for (int k0 = 0; k0 < HDc; k0 += 64, buf ^= 1) {
        CP_WAIT0;
        __syncthreads();

        if (k0 + 64 < HDc) {
            int nb = buf ^ 1;
#pragma unroll
            for (int it = 0; it < 4; it++) {
                int i = tid + it * 256; int m = i >> 3; int ch = i & 7;
                cp16(smo + O_A(nb) + m * 144 + ch * 16,
                     A + (size_t)(m0 + m) * HDc + k0 + 64 + ch * 8);
            }
#pragma unroll
            for (int it = 0; it < 4; it++) {
                int i = tid + it * 256; int row = i >> 3; int ch = i & 7;
                cp16(smo + O_B(nb) + row * 144 + ch * 16,
                     B + (size_t)(ncol0 + row) * HDc + k0 + 64 + ch * 8);
            }
            CP_COMMIT;
        }

        const unsigned aB = sb + O_A(buf) + aOff;
        const unsigned bB = sb + O_B(buf) + bOff;
#pragma unroll
        for (int kk = 0; kk < 4; kk++) {
            unsigned af[2][4], bf[4][4];
            ldsm4(af[0], aB + kk * 32);
            ldsm4(af[1], aB + 16 * 144 + kk * 32);
#pragma unroll
            for (int p = 0; p < 4; p++)
                ldsm4(bf[p], bB + p * 16 * 144 + kk * 32);
#pragma unroll
            for (int nt = 0; nt < 8; nt++) {
                unsigned b0 = bf[nt >> 1][nt & 1];
                unsigned b1 = bf[nt >> 1][2 + (nt & 1)];
#pragma unroll
                for (int mt = 0; mt < 2; mt++)
                    mma16(acc[mt][nt], af[mt], b0, b1);
            }
        }
    }

#pragma unroll
    for (int mt = 0; mt < 2; mt++) {
        int mrow = m0 + wm * 32 + mt * 16 + r;
#pragma unroll
        for (int nt = 0; nt < 8; nt++) {
            int d = ncol0 + wn * 64 + nt * 8 + 2 * c;
            float bb0 = bo[d], bb1 = bo[d + 1];
            *(float2*)(outp + (size_t)mrow * Ec + d) =
                make_float2(acc[mt][nt][0] + bb0, acc[mt][nt][1] + bb1);
            *(float2*)(outp + (size_t)(mrow + 8) * Ec + d) =
                make_float2(acc[mt][nt][2] + bb0, acc[mt][nt][3] + bb1);
        }
    }
}

// ---------------------------------------------------------------------------
// Kernel 2: flash attention (R14 best config: BQ=128, 8 warps, occ 2).
// exp2 domain, diagonal-only masking, deferred l-reduction, reversed order.
// smem: K0@0 V0@9216 | K1@18432 V1@27648 -> 36864 B
// ---------------------------------------------------------------------------
#define F_SMEM 36864
#define SCL 0.18033688011112042f   // 0.125 * log2(e)

__device__ __forceinline__ void stage_kv_h(char* s, int base,
                                           const __half* Kb, const __half* Vb,
                                           int k0, int tid)
{
#pragma unroll
    for (int it = 0; it < 2; it++) {
        int i = tid + it * 256;
        int row = i >> 3, ch = i & 7;
        cp16(s + base + row * 144 + ch * 16,        Kb + (size_t)(k0 + row) * Dc + ch * 8);
        cp16(s + base + 9216 + row * 144 + ch * 16, Vb + (size_t)(k0 + row) * Dc + ch * 8);
    }
}

__global__ __launch_bounds__(256, 2) void flash_fp16_kernel()
{
    extern __shared__ __align__(16) char smf[];
    const unsigned sb = (unsigned)__cvta_generic_to_shared(smf);

    const int bh = blockIdx.y;
    const int b  = bh >> 4, h = bh & 15;
    const int bx = gridDim.x - 1 - blockIdx.x;     // heavy tiles first
    const int q0 = bx * 128;

    const __half* __restrict__ Qb = g_Qh + (size_t)bh * Sc * Dc;
    const __half* __restrict__ Kb = g_Kh + (size_t)bh * Sc * Dc;
    const __half* __restrict__ Vb = g_Vh + (size_t)bh * Sc * Dc;

    const int tid  = threadIdx.x;
    const int warp = tid >> 5, lane = tid & 31;
    const int r = lane >> 2, c = lane & 3;
    const int ln15 = lane & 15, lhiB = (lane >> 4) * 16;

#pragma unroll
    for (int it = 0; it < 4; it++) {
        int i = tid + it * 256;
        int row = i >> 3, ch = i & 7;
        cp16(smf + row * 144 + ch * 16, Qb + (size_t)(q0 + row) * Dc + ch * 8);
    }
    CP_COMMIT; CP_WAIT0;
    __syncthreads();

    unsigned qf[4][4];
    {
        const unsigned qB = sb + (unsigned)((warp * 16 + ln15) * 144) + lhiB;
#pragma unroll
        for (int kk = 0; kk < 4; kk++)
            ldsm4(qf[kk], qB + kk * 32);
    }
    __syncthreads();

    const int nkt = 2 * (bx + 1);
    stage_kv_h(smf, 0, Kb, Vb, 0, tid);
    CP_COMMIT;

    float of[8][4];
#pragma unroll
    for (int nt = 0; nt < 8; nt++)
#pragma unroll
        for (int j = 0; j < 4; j++) of[nt][j] = 0.0f;
    float m_lo = -1e30f, m_hi = -1e30f, l_lo = 0.0f, l_hi = 0.0f;

    const int qwmin = q0 + warp * 16;
    const int qlo = qwmin + r;
    const int qhi = qlo + 8;
    const int qmax = qwmin + 15;

    const int lm = lane >> 3, lr8 = lane & 7;

    int buf = 0;
    for (int kt = 0; kt < nkt; kt++) {
        CP_WAIT0;
        __syncthreads();
        if (kt + 1 < nkt) {
            stage_kv_h(smf, (buf ^ 1) * 18432, Kb, Vb, (kt + 1) * 64, tid);
            CP_COMMIT;
        }
        const int kbase = kt * 64;
        if (kbase <= qmax) {
            const unsigned kB = sb + buf * 18432 + (unsigned)(ln15 * 144) + lhiB;
            const unsigned vbase = sb + buf * 18432 + 9216;

            // S = Q K^T
            float sf[8][4];
#pragma unroll
            for (int nt = 0; nt < 8; nt++)
                sf[nt][0] = sf[nt][1] = sf[nt][2] = sf[nt][3] = 0.0f;
#pragma unroll
            for (int kk = 0; kk < 4; kk++) {
                unsigned kf[4][4];
#pragma unroll
                for (int p = 0; p < 4; p++)
                    ldsm4(kf[p], kB + p * 16 * 144 + kk * 32);
#pragma unroll
                for (int nt = 0; nt < 8; nt++)
                    mma16(sf[nt], qf[kk], kf[nt >> 1][nt & 1], kf[nt >> 1][2 + (nt & 1)]);
            }

            // scale (log2 domain); mask only diagonal tiles (warp-uniform)
            float mx_lo = -1e30f, mx_hi = -1e30f;
            if (kbase + 63 > qwmin) {
#pragma unroll
                for (int nt = 0; nt < 8; nt++) {
                    int kg0 = kbase + nt * 8 + 2 * c;
                    int kg1 = kg0 + 1;
                    float s0 = sf[nt][0] * SCL; if (kg0 > qlo) s0 = -1e30f;
                    float s1 = sf[nt][1] * SCL; if (kg1 > qlo) s1 = -1e30f;
                    float s2 = sf[nt][2] * SCL; if (kg0 > qhi) s2 = -1e30f;
                    float s3 = sf[nt][3] * SCL; if (kg1 > qhi) s3 = -1e30f;
                    sf[nt][0] = s0; sf[nt][1] = s1; sf[nt][2] = s2; sf[nt][3] = s3;
                    mx_lo = fmaxf(mx_lo, fmaxf(s0, s1));
                    mx_hi = fmaxf(mx_hi, fmaxf(s2, s3));
                }
            } else {
#pragma unroll
                for (int nt = 0; nt < 8; nt++) {
                    float s0 = sf[nt][0] * SCL;
                    float s1 = sf[nt][1] * SCL;
                    float s2 = sf[nt][2] * SCL;
                    float s3 = sf[nt][3] * SCL;
                    sf[nt][0] = s0; sf[nt][1] = s1; sf[nt][2] = s2; sf[nt][3] = s3;
                    mx_lo = fmaxf(mx_lo, fmaxf(s0, s1));
                    mx_hi = fmaxf(mx_hi, fmaxf(s2, s3));
                }
            }
            mx_lo = fmaxf(mx_lo, __shfl_xor_sync(0xffffffffu, mx_lo, 1));
            mx_lo = fmaxf(mx_lo, __shfl_xor_sync(0xffffffffu, mx_lo, 2));
            mx_hi = fmaxf(mx_hi, __shfl_xor_sync(0xffffffffu, mx_hi, 1));
            mx_hi = fmaxf(mx_hi, __shfl_xor_sync(0xffffffffu, mx_hi, 2));

            float mn_lo = fmaxf(m_lo, mx_lo), mn_hi = fmaxf(m_hi, mx_hi);
            float a_lo = ex2(m_lo - mn_lo), a_hi = ex2(m_hi - mn_hi);

            unsigned pr0[8], pr1[8];
            float ps_lo = 0.0f, ps_hi = 0.0f;
#pragma unroll
            for (int nt = 0; nt < 8; nt++) {
                float p0 = ex2(sf[nt][0] - mn_lo);
                float p1 = ex2(sf[nt][1] - mn_lo);
                float p2 = ex2(sf[nt][2] - mn_hi);
                float p3 = ex2(sf[nt][3] - mn_hi);
                ps_lo += p0 + p1;  ps_hi += p2 + p3;
                pr0[nt] = pk(p0, p1);
                pr1[nt] = pk(p2, p3);
            }
            l_lo = l_lo * a_lo + ps_lo;
            l_hi = l_hi * a_hi + ps_hi;
            m_lo = mn_lo; m_hi = mn_hi;

#pragma unroll
            for (int nt = 0; nt < 8; nt++) {
                of[nt][0] *= a_lo; of[nt][1] *= a_lo;
                of[nt][2] *= a_hi; of[nt][3] *= a_hi;
            }

            // O += P V
#pragma unroll
            for (int kk = 0; kk < 4; kk++) {
                unsigned pa[4] = { pr0[2 * kk], pr1[2 * kk],
                                   pr0[2 * kk + 1], pr1[2 * kk + 1] };
#pragma unroll
                for (int ntp = 0; ntp < 4; ntp++) {
                    unsigned vf[4];
                    unsigned va = vbase
                        + (unsigned)((kk * 16 + (lm & 1) * 8 + lr8) * 144)
                        + (unsigned)((ntp * 16 + (lm >> 1) * 8) * 2);
                    ldsm4t(vf, va);
                    mma16(of[2 * ntp],     pa, vf[0], vf[1]);
                    mma16(of[2 * ntp + 1], pa, vf[2], vf[3]);
                }
            }
        }
        buf ^= 1;
    }

    // final l reduction across the quad
    l_lo += __shfl_xor_sync(0xffffffffu, l_lo, 1);
    l_lo += __shfl_xor_sync(0xffffffffu, l_lo, 2);
    l_hi += __shfl_xor_sync(0xffffffffu, l_hi, 1);
    l_hi += __shfl_xor_sync(0xffffffffu, l_hi, 2);

    float il_lo = 1.0f / l_lo, il_hi = 1.0f / l_hi;
    size_t rb_lo = ((size_t)b * Sc + qlo) * HDc + h * Dc;
    size_t rb_hi = ((size_t)b * Sc + qhi) * HDc + h * Dc;
#pragma unroll
    for (int nt = 0; nt < 8; nt++) {
        int d = nt * 8 + 2 * c;
        *(unsigned*)(g_AOh + rb_lo + d) = pk(of[nt][0] * il_lo, of[nt][1] * il_lo);
        *(unsigned*)(g_AOh + rb_hi + d) = pk(of[nt][2] * il_hi, of[nt][3] * il_hi);
    }
}

// ---------------------------------------------------------------------------
extern "C" void kernel_launch(void* const* d_in, const int* in_sizes, int n_in,
                              void* d_out, int out_size)
{
    const float* x  = (const float*)d_in[0];
    const float* Wq = (const float*)d_in[1];
    const float* bq = (const float*)d_in[2];
    const float* Wk = (const float*)d_in[3];
    const float* bk = (const float*)d_in[4];
    const float* Wv = (const float*)d_in[5];
    const float* bv = (const float*)d_in[6];
    const float* Wo = (const float*)d_in[7];
    const float* bo = (const float*)d_in[8];
    float* out = (float*)d_out;

    cudaFuncSetAttribute(qkv_fp16_kernel,
                         cudaFuncAttributeMaxDynamicSharedMemorySize, QKV_SMEM);
    cudaFuncSetAttribute(flash_fp16_kernel,
                         cudaFuncAttributeMaxDynamicSharedMemorySize, F_SMEM);
    cudaFuncSetAttribute(out_fp16_kernel,
                         cudaFuncAttributeMaxDynamicSharedMemorySize, O_SMEM);

    prepass_kernel<<<4608, 256>>>(x, Wq, Wk, Wv, Wo);

    dim3 g1(Mc / 128, Hc);
    qkv_fp16_kernel<<<g1, 256, QKV_SMEM>>>(bq, bk, bv);

    dim3 g2(Sc / 128, Bc * Hc);
    flash_fp16_kernel<<<g2, 256, F_SMEM>>>();

    dim3 g3(Ec / 128, Mc / 128);
    out_fp16_kernel<<<g3, 256, O_SMEM>>>(bo, out);
}

// round 17
// speedup vs baseline: 1.0413x; 1.0017x over previous
#include <cuda_runtime.h>
#include <cuda_fp16.h>
#include <cstdint>

// Problem dims (fixed)
#define Bc  4
#define Sc  2048
#define Ec  1024
#define Hc  16
#define Dc  64
#define HDc (Hc * Dc)      // 1024
#define Mc  (Bc * Sc)      // 8192

// Scratch (fp16 pipeline)
__device__ __half g_Qh[Bc * Hc * Sc * Dc];
__device__ __half g_Kh[Bc * Hc * Sc * Dc];
__device__ __half g_Vh[Bc * Hc * Sc * Dc];
__device__ __half g_AOh[Bc * Sc * HDc];
__device__ __half g_xh [Mc * Ec];
__device__ __half g_Wqt[Hc * Dc * Ec];   // transposed [h][d][e]
__device__ __half g_Wkt[Hc * Dc * Ec];
__device__ __half g_Wvt[Hc * Dc * Ec];
__device__ __half g_Wot[Ec * HDc];       // transposed [n][k]

// ---------------------------------------------------------------------------
// helpers
// ---------------------------------------------------------------------------
__device__ __forceinline__ unsigned pk(float a, float b) {
    __half2 h = __floats2half2_rn(a, b);
    return *reinterpret_cast<unsigned*>(&h);
}

__device__ __forceinline__ float ex2(float x) {
    float y;
    asm("ex2.approx.f32 %0, %1;" : "=f"(y) : "f"(x));
    return y;
}

__device__ __forceinline__ void mma16(float* d, const unsigned* a, unsigned b0, unsigned b1) {
    asm volatile(
        "mma.sync.aligned.m16n8k16.row.col.f32.f16.f16.f32 "
        "{%0,%1,%2,%3}, {%4,%5,%6,%7}, {%8,%9}, {%0,%1,%2,%3};"
        : "+f"(d[0]), "+f"(d[1]), "+f"(d[2]), "+f"(d[3])
        : "r"(a[0]), "r"(a[1]), "r"(a[2]), "r"(a[3]), "r"(b0), "r"(b1));
}

__device__ __forceinline__ void ldsm4(unsigned* f, unsigned addr_bytes) {
    asm volatile("ldmatrix.sync.aligned.m8n8.x4.shared.b16 {%0,%1,%2,%3}, [%4];"
        : "=r"(f[0]), "=r"(f[1]), "=r"(f[2]), "=r"(f[3]) : "r"(addr_bytes));
}
__device__ __forceinline__ void ldsm4t(unsigned* f, unsigned addr_bytes) {
    asm volatile("ldmatrix.sync.aligned.m8n8.x4.trans.shared.b16 {%0,%1,%2,%3}, [%4];"
        : "=r"(f[0]), "=r"(f[1]), "=r"(f[2]), "=r"(f[3]) : "r"(addr_bytes));
}

__device__ __forceinline__ void cp16(void* smem, const void* g) {
    unsigned sa = (unsigned)__cvta_generic_to_shared(smem);
    asm volatile("cp.async.cg.shared.global [%0], [%1], 16;" :: "r"(sa), "l"(g));
}
#define CP_COMMIT asm volatile("cp.async.commit_group;")
#define CP_WAIT0  asm volatile("cp.async.wait_group 0;")

// ---------------------------------------------------------------------------
// Prepass (ONE launch): blocks [0,3072) Wq/Wk/Wv transpose,
// [3072,4096) Wo transpose, [4096,5632) x fp32->fp16 grid-stride.
// ---------------------------------------------------------------------------
__global__ __launch_bounds__(256) void prepass_kernel(
    const float* __restrict__ x,
    const float* __restrict__ Wq, const float* __restrict__ Wk,
    const float* __restrict__ Wv, const float* __restrict__ Wo)
{
    __shared__ float t[32][33];
    const int blk = blockIdx.x;
    const int tx = threadIdx.x & 31, ty = threadIdx.x >> 5;

    if (blk < 3072) {
        const int xb = blk & 1, yb = (blk >> 1) & 31, z = blk >> 6;
        const int mat = z >> 4, h = z & 15;
        const float* S = ((mat == 0) ? Wq : (mat == 1) ? Wk : Wv) + (size_t)h * Ec * Dc;
        __half* D = ((mat == 0) ? g_Wqt : (mat == 1) ? g_Wkt : g_Wvt) + (size_t)h * Dc * Ec;
        int c0 = xb * 32, r0 = yb * 32;
#pragma unroll
        for (int i = 0; i < 32; i += 8)
            t[ty + i][tx] = S[(size_t)(r0 + ty + i) * Dc + c0 + tx];
        __syncthreads();
#pragma unroll
        for (int i = 0; i < 32; i += 8)
            D[(size_t)(c0 + ty + i) * Ec + r0 + tx] = __float2half_rn(t[tx][ty + i]);
    } else if (blk < 4096) {
        const int idx2 = blk - 3072;
        int c0 = (idx2 & 31) * 32, r0 = (idx2 >> 5) * 32;
#pragma unroll
        for (int i = 0; i < 32; i += 8)
            t[ty + i][tx] = Wo[(size_t)(r0 + ty + i) * Ec + c0 + tx];
        __syncthreads();
#pragma unroll
        for (int i = 0; i < 32; i += 8)
            g_Wot[(size_t)(c0 + ty + i) * HDc + r0 + tx] = __float2half_rn(t[tx][ty + i]);
    } else {
        const float4* src = (const float4*)x;
        uint2* dst = (uint2*)g_xh;
        const int n4 = Mc * Ec / 4;
        for (int i = (blk - 4096) * 256 + threadIdx.x; i < n4; i += 1536 * 256) {
            float4 v = src[i];
            dst[i] = make_uint2(pk(v.x, v.y), pk(v.z, v.w));
        }
    }
}

// ---------------------------------------------------------------------------
// Kernel 1: FUSED QKV projection (frozen — at mma.sync roofline).
// Block 128(M) x 192(N) x 64(K halves). 256 thr = 8 warps (4m x 2n),
// warp tile 32x96. Rows 144 B. smem: A0@0 A1@18432 | B0@36864 B1@64512
// ---------------------------------------------------------------------------
#define QKV_A(b) ((b) * 18432)
#define QKV_B(b) (36864 + (b) * 27648)
#define QKV_SMEM 92160

__global__ __launch_bounds__(256, 1) void qkv_fp16_kernel(
    const float* __restrict__ bq, const float* __restrict__ bk,
    const float* __restrict__ bv)
{
    extern __shared__ __align__(16) char smq[];
    const unsigned sb = (unsigned)__cvta_generic_to_shared(smq);

    const int tid  = threadIdx.x;
    const int warp = tid >> 5, lane = tid & 31;
    const int wm = warp >> 1, wn = warp & 1;
    const int r = lane >> 2, c = lane & 3;
    const int ln15 = lane & 15, lhiB = (lane >> 4) * 16;
    const int m0 = blockIdx.x * 128;
    const int h  = blockIdx.y;

    const __half* __restrict__ W0 = g_Wqt + (size_t)h * Dc * Ec;
    const __half* __restrict__ W1 = g_Wkt + (size_t)h * Dc * Ec;
    const __half* __restrict__ W2 = g_Wvt + (size_t)h * Dc * Ec;
    const __half* __restrict__ xh = g_xh;

#pragma unroll
    for (int it = 0; it < 4; it++) {
        int i = tid + it * 256; int m = i >> 3; int ch = i & 7;
        cp16(smq + QKV_A(0) + m * 144 + ch * 16, xh + (size_t)(m0 + m) * Ec + ch * 8);
    }
#pragma unroll
    for (int it = 0; it < 6; it++) {
        int i = tid + it * 256; int row = i >> 3; int ch = i & 7;
        const __half* w = (row < 64) ? W0 : (row < 128) ? W1 : W2;
        cp16(smq + QKV_B(0) + row * 144 + ch * 16, w + (size_t)(row & 63) * Ec + ch * 8);
    }
    CP_COMMIT;

    float acc[2][12][4];
#pragma unroll
    for (int mt = 0; mt < 2; mt++)
#pragma unroll
        for (int nt = 0; nt < 12; nt++)
#pragma unroll
            for (int j = 0; j < 4; j++) acc[mt][nt][j] = 0.0f;

    const unsigned aOff = (unsigned)((wm * 32 + ln15) * 144) + lhiB;
    const unsigned bOff = (unsigned)((wn * 96 + ln15) * 144) + lhiB;

    int buf = 0;
    for (int k0 = 0; k0 < Ec; k0 += 64, buf ^= 1) {
        CP_WAIT0;
        __syncthreads();

        if (k0 + 64 < Ec) {
            int nb = buf ^ 1;
#pragma unroll
            for (int it = 0; it < 4; it++) {
                int i = tid + it * 256; int m = i >> 3; int ch = i & 7;
                cp16(smq + QKV_A(nb) + m * 144 + ch * 16,
                     xh + (size_t)(m0 + m) * Ec + k0 + 64 + ch * 8);
            }
#pragma unroll
            for (int it = 0; it < 6; it++) {
                int i = tid + it * 256; int row = i >> 3; int ch = i & 7;
                const __half* w = (row < 64) ? W0 : (row < 128) ? W1 : W2;
                cp16(smq + QKV_B(nb) + row * 144 + ch * 16,
                     w + (size_t)(row & 63) * Ec + k0 + 64 + ch * 8);
            }
            CP_COMMIT;
        }

        const unsigned aB = sb + QKV_A(buf) + aOff;
        const unsigned bB = sb + QKV_B(buf) + bOff;
#pragma unroll
        for (int kk = 0; kk < 4; kk++) {
            unsigned af[2][4], bf[6][4];
            ldsm4(af[0], aB + kk * 32);
            ldsm4(af[1], aB + 16 * 144 + kk * 32);
#pragma unroll
            for (int p = 0; p < 6; p++)
                ldsm4(bf[p], bB + p * 16 * 144 + kk * 32);
#pragma unroll
            for (int nt = 0; nt < 12; nt++) {
                unsigned b0 = bf[nt >> 1][nt & 1];
                unsigned b1 = bf[nt >> 1][2 + (nt & 1)];
#pragma unroll
                for (int mt = 0; mt < 2; mt++)
                    mma16(acc[mt][nt], af[mt], b0, b1);
            }
        }
    }

    const int bI = m0 >> 11;
    const int sBase = m0 & 2047;
#pragma unroll
    for (int nt = 0; nt < 12; nt++) {
        int g   = wn * 96 + nt * 8;
        int mat = g >> 6;
        int d   = (g & 63) + 2 * c;
        __half* Out = (mat == 0) ? g_Qh : (mat == 1) ? g_Kh : g_Vh;
        const float* bias = (mat == 0) ? bq : (mat == 1) ? bk : bv;
        float bb0 = bias[h * Dc + d], bb1 = bias[h * Dc + d + 1];
#pragma unroll
        for (int mt = 0; mt < 2; mt++) {
            int lr = wm * 32 + mt * 16 + r;
            size_t base = ((((size_t)bI * Hc + h) * Sc) + sBase + lr) * Dc + d;
            *(unsigned*)(Out + base)          = pk(acc[mt][nt][0] + bb0, acc[mt][nt][1] + bb1);
            *(unsigned*)(Out + base + 8 * Dc) = pk(acc[mt][nt][2] + bb0, acc[mt][nt][3] + bb1);
        }
    }
}

// ---------------------------------------------------------------------------
// Kernel 3: output projection (R16 config, frozen: 128x128x64h, occ 2).
// ---------------------------------------------------------------------------
#define O_A(b) ((b) * 18432)
#define O_B(b) (36864 + (b) * 18432)
#define O_SMEM 73728

__global__ __launch_bounds__(256, 2) void out_fp16_kernel(
    const float* __restrict__ bo, float* __restrict__ outp)
{
    extern __shared__ __align__(16) char smo[];
    const unsigned sb = (unsigned)__cvta_generic_to_shared(smo);

    const __half* __restrict__ A = (const __half*)g_AOh;
    const __half* __restrict__ B = (const __half*)g_Wot;

    const int tid  = threadIdx.x;
    const int warp = tid >> 5, lane = tid & 31;
    const int wm = warp >> 1, wn = warp & 1;
    const int r = lane >> 2, c = lane & 3;
    const int ln15 = lane & 15, lhiB = (lane >> 4) * 16;
    const int m0 = blockIdx.y * 128;
    const int ncol0 = blockIdx.x * 128;

#pragma unroll
    for (int it = 0; it < 4; it++) {
        int i = tid + it * 256; int m = i >> 3; int ch = i & 7;
        cp16(smo + O_A(0) + m * 144 + ch * 16, A + (size_t)(m0 + m) * HDc + ch * 8);
    }
#pragma unroll
    for (int it = 0; it < 4; it++) {
        int i = tid + it * 256; int row = i >> 3; int ch = i & 7;
        cp16(smo + O_B(0) + row * 144 + ch * 16,
             B + (size_t)(ncol0 + row) * HDc + ch * 8);
    }
    CP_COMMIT;

    float acc[2][8][4];
#pragma unroll
    for (int mt = 0; mt < 2; mt++)
#pragma unroll
        for (int nt = 0; nt < 8; nt++)
#pragma unroll
            for (int j = 0; j < 4; j++) acc[mt][nt][j] = 0.0f;

    const unsigned aOff = (unsigned)((wm * 32 + ln15) * 144) + lhiB;
    const unsigned bOff = (unsigned)((wn * 64 + ln15) * 144) + lhiB;

    int buf = 0;
    for (int k0 = 0; k0 < HDc; k0 += 64, buf ^= 1) {
        CP_WAIT0;
        __syncthreads();

        if (k0 + 64 < HDc) {
            int nb = buf ^ 1;
#pragma unroll
            for (int it = 0; it < 4; it++) {
                int i = tid + it * 256; int m = i >> 3; int ch = i & 7;
                cp16(smo + O_A(nb) + m * 144 + ch * 16,
                     A + (size_t)(m0 + m) * HDc + k0 + 64 + ch * 8);
            }
#pragma unroll
            for (int it = 0; it < 4; it++) {
                int i = tid + it * 256; int row = i >> 3; int ch = i & 7;
                cp16(smo + O_B(nb) + row * 144 + ch * 16,
                     B + (size_t)(ncol0 + row) * HDc + k0 + 64 + ch * 8);
            }
            CP_COMMIT;
        }

        const unsigned aB = sb + O_A(buf) + aOff;
        const unsigned bB = sb + O_B(buf) + bOff;
#pragma unroll
        for (int kk = 0; kk < 4; kk++) {
            unsigned af[2][4], bf[4][4];
            ldsm4(af[0], aB + kk * 32);
            ldsm4(af[1], aB + 16 * 144 + kk * 32);
#pragma unroll
            for (int p = 0; p < 4; p++)
                ldsm4(bf[p], bB + p * 16 * 144 + kk * 32);
#pragma unroll
            for (int nt = 0; nt < 8; nt++) {
                unsigned b0 = bf[nt >> 1][nt & 1];
                unsigned b1 = bf[nt >> 1][2 + (nt & 1)];
#pragma unroll
                for (int mt = 0; mt < 2; mt++)
                    mma16(acc[mt][nt], af[mt], b0, b1);
            }
        }
    }

#pragma unroll
    for (int mt = 0; mt < 2; mt++) {
        int mrow = m0 + wm * 32 + mt * 16 + r;
#pragma unroll
        for (int nt = 0; nt < 8; nt++) {
            int d = ncol0 + wn * 64 + nt * 8 + 2 * c;
            float bb0 = bo[d], bb1 = bo[d + 1];
            *(float2*)(outp + (size_t)mrow * Ec + d) =
                make_float2(acc[mt][nt][0] + bb0, acc[mt][nt][1] + bb1);
            *(float2*)(outp + (size_t)(mrow + 8) * Ec + d) =
                make_float2(acc[mt][nt][2] + bb0, acc[mt][nt][3] + bb1);
        }
    }
}

// ---------------------------------------------------------------------------
// Kernel 2: flash attention. BQ=128, 8 warps, occ 2 (two independent barrier
// domains — proven required). BKT=128 per STAGE (two 64-col sub-tiles per
// stage) -> HALF the wait/sync/stage rounds. Causal skip per 64 sub-tile.
// smem: buf K@0(128x144) V@18432(128x144) | buf1 @36864 -> 73728 B/CTA.
// ---------------------------------------------------------------------------
#define F_SMEM 73728
#define SCL 0.18033688011112042f   // 0.125 * log2(e)

__device__ __forceinline__ void stage_kv128(char* s, int base,
                                            const __half* Kb, const __half* Vb,
                                            int k0, int tid)
{
#pragma unroll
    for (int it = 0; it < 4; it++) {
        int i = tid + it * 256;
        int row = i >> 3, ch = i & 7;    // 128 rows x 8 chunks
        cp16(s + base + row * 144 + ch * 16,         Kb + (size_t)(k0 + row) * Dc + ch * 8);
        cp16(s + base + 18432 + row * 144 + ch * 16, Vb + (size_t)(k0 + row) * Dc + ch * 8);
    }
}

__global__ __launch_bounds__(256, 2) void flash_fp16_kernel()
{
    extern __shared__ __align__(16) char smf[];
    const unsigned sb = (unsigned)__cvta_generic_to_shared(smf);

    const int bh = blockIdx.y;
    const int b  = bh >> 4, h = bh & 15;
    const int bx = gridDim.x - 1 - blockIdx.x;     // heavy tiles first
    const int q0 = bx * 128;

    const __half* __restrict__ Qb = g_Qh + (size_t)bh * Sc * Dc;
    const __half* __restrict__ Kb = g_Kh + (size_t)bh * Sc * Dc;
    const __half* __restrict__ Vb = g_Vh + (size_t)bh * Sc * Dc;

    const int tid  = threadIdx.x;
    const int warp = tid >> 5, lane = tid & 31;
    const int r = lane >> 2, c = lane & 3;
    const int ln15 = lane & 15, lhiB = (lane >> 4) * 16;

    // stage Q transiently in buf0, extract A-fragments
#pragma unroll
    for (int it = 0; it < 4; it++) {
        int i = tid + it * 256;
        int row = i >> 3, ch = i & 7;
        cp16(smf + row * 144 + ch * 16, Qb + (size_t)(q0 + row) * Dc + ch * 8);
    }
    CP_COMMIT; CP_WAIT0;
    __syncthreads();

    unsigned qf[4][4];
    {
        const unsigned qB = sb + (unsigned)((warp * 16 + ln15) * 144) + lhiB;
#pragma unroll
        for (int kk = 0; kk < 4; kk++)
            ldsm4(qf[kk], qB + kk * 32);
    }
    __syncthreads();

    const int nkt = bx + 1;               // 128-wide stages
    stage_kv128(smf, 0, Kb, Vb, 0, tid);
    CP_COMMIT;

    float of[8][4];
#pragma unroll
    for (int nt = 0; nt < 8; nt++)
#pragma unroll
        for (int j = 0; j < 4; j++) of[nt][j] = 0.0f;
    float m_lo = -1e30f, m_hi = -1e30f, l_lo = 0.0f, l_hi = 0.0f;

    const int qwmin = q0 + warp * 16;
    const int qlo = qwmin + r;
    const int qhi = qlo + 8;
    const int qmax = qwmin + 15;

    const int lm = lane >> 3, lr8 = lane & 7;

    int buf = 0;
    for (int kt = 0; kt < nkt; kt++) {
        CP_WAIT0;
        __syncthreads();
        if (kt + 1 < nkt) {
            stage_kv128(smf, (buf ^ 1) * 36864, Kb, Vb, (kt + 1) * 128, tid);
            CP_COMMIT;
        }

#pragma unroll
        for (int sub = 0; sub < 2; sub++) {
            const int ksub = kt * 128 + sub * 64;
            if (ksub > qmax) continue;     // warp-uniform 64-granular skip

            const unsigned kB = sb + buf * 36864
                              + (unsigned)((sub * 64 + ln15) * 144) + lhiB;
            const unsigned vbase = sb + buf * 36864 + 18432 + (unsigned)(sub * 64 * 144);

            // S = Q K^T
            float sf[8][4];
#pragma unroll
            for (int nt = 0; nt < 8; nt++)
                sf[nt][0] = sf[nt][1] = sf[nt][2] = sf[nt][3] = 0.0f;
#pragma unroll
            for (int kk = 0; kk < 4; kk++) {
                unsigned kf[4][4];
#pragma unroll
                for (int p = 0; p < 4; p++)
                    ldsm4(kf[p], kB + p * 16 * 144 + kk * 32);
#pragma unroll
                for (int nt = 0; nt < 8; nt++)
                    mma16(sf[nt], qf[kk], kf[nt >> 1][nt & 1], kf[nt >> 1][2 + (nt & 1)]);
            }

            // scale (log2 domain); mask only diagonal sub-tiles (warp-uniform)
            float mx_lo = -1e30f, mx_hi = -1e30f;
            if (ksub + 63 > qwmin) {
#pragma unroll
                for (int nt = 0; nt < 8; nt++) {
                    int kg0 = ksub + nt * 8 + 2 * c;
                    int kg1 = kg0 + 1;
                    float s0 = sf[nt][0] * SCL; if (kg0 > qlo) s0 = -1e30f;
                    float s1 = sf[nt][1] * SCL; if (kg1 > qlo) s1 = -1e30f;
                    float s2 = sf[nt][2] * SCL; if (kg0 > qhi) s2 = -1e30f;
                    float s3 = sf[nt][3] * SCL; if (kg1 > qhi) s3 = -1e30f;
                    sf[nt][0] = s0; sf[nt][1] = s1; sf[nt][2] = s2; sf[nt][3] = s3;
                    mx_lo = fmaxf(mx_lo, fmaxf(s0, s1));
                    mx_hi = fmaxf(mx_hi, fmaxf(s2, s3));
                }
            } else {
#pragma unroll
                for (int nt = 0; nt < 8; nt++) {
                    float s0 = sf[nt][0] * SCL;
                    float s1 = sf[nt][1] * SCL;
                    float s2 = sf[nt][2] * SCL;
                    float s3 = sf[nt][3] * SCL;
                    sf[nt][0] = s0; sf[nt][1] = s1; sf[nt][2] = s2; sf[nt][3] = s3;
                    mx_lo = fmaxf(mx_lo, fmaxf(s0, s1));
                    mx_hi = fmaxf(mx_hi, fmaxf(s2, s3));
                }
            }
            mx_lo = fmaxf(mx_lo, __shfl_xor_sync(0xffffffffu, mx_lo, 1));
            mx_lo = fmaxf(mx_lo, __shfl_xor_sync(0xffffffffu, mx_lo, 2));
            mx_hi = fmaxf(mx_hi, __shfl_xor_sync(0xffffffffu, mx_hi, 1));
            mx_hi = fmaxf(mx_hi, __shfl_xor_sync(0xffffffffu, mx_hi, 2));

            float mn_lo = fmaxf(m_lo, mx_lo), mn_hi = fmaxf(m_hi, mx_hi);
            float a_lo = ex2(m_lo - mn_lo), a_hi = ex2(m_hi - mn_hi);

            unsigned pr0[8], pr1[8];
            float ps_lo = 0.0f, ps_hi = 0.0f;
#pragma unroll
            for (int nt = 0; nt < 8; nt++) {
                float p0 = ex2(sf[nt][0] - mn_lo);
                float p1 = ex2(sf[nt][1] - mn_lo);
                float p2 = ex2(sf[nt][2] - mn_hi);
                float p3 = ex2(sf[nt][3] - mn_hi);
                ps_lo += p0 + p1;  ps_hi += p2 + p3;
                pr0[nt] = pk(p0, p1);
                pr1[nt] = pk(p2, p3);
            }
            l_lo = l_lo * a_lo + ps_lo;
            l_hi = l_hi * a_hi + ps_hi;
            m_lo = mn_lo; m_hi = mn_hi;

#pragma unroll
            for (int nt = 0; nt < 8; nt++) {
                of[nt][0] *= a_lo; of[nt][1] *= a_lo;
                of[nt][2] *= a_hi; of[nt][3] *= a_hi;
            }

            // O += P V
#pragma unroll
            for (int kk = 0; kk < 4; kk++) {
                unsigned pa[4] = { pr0[2 * kk], pr1[2 * kk],
                                   pr0[2 * kk + 1], pr1[2 * kk + 1] };
#pragma unroll
                for (int ntp = 0; ntp < 4; ntp++) {
                    unsigned vf[4];
                    unsigned va = vbase
                        + (unsigned)((kk * 16 + (lm & 1) * 8 + lr8) * 144)
                        + (unsigned)((ntp * 16 + (lm >> 1) * 8) * 2);
                    ldsm4t(vf, va);
                    mma16(of[2 * ntp],     pa, vf[0], vf[1]);
                    mma16(of[2 * ntp + 1], pa, vf[2], vf[3]);
                }
            }
        }
        buf ^= 1;
    }

    // final l reduction across the quad
    l_lo += __shfl_xor_sync(0xffffffffu, l_lo, 1);
    l_lo += __shfl_xor_sync(0xffffffffu, l_lo, 2);
    l_hi += __shfl_xor_sync(0xffffffffu, l_hi, 1);
    l_hi += __shfl_xor_sync(0xffffffffu, l_hi, 2);

    float il_lo = 1.0f / l_lo, il_hi = 1.0f / l_hi;
    size_t rb_lo = ((size_t)b * Sc + qlo) * HDc + h * Dc;
    size_t rb_hi = ((size_t)b * Sc + qhi) * HDc + h * Dc;
#pragma unroll
    for (int nt = 0; nt < 8; nt++) {
        int d = nt * 8 + 2 * c;
        *(unsigned*)(g_AOh + rb_lo + d) = pk(of[nt][0] * il_lo, of[nt][1] * il_lo);
        *(unsigned*)(g_AOh + rb_hi + d) = pk(of[nt][2] * il_hi, of[nt][3] * il_hi);
    }
}

// ---------------------------------------------------------------------------
extern "C" void kernel_launch(void* const* d_in, const int* in_sizes, int n_in,
                              void* d_out, int out_size)
{
    const float* x  = (const float*)d_in[0];
    const float* Wq = (const float*)d_in[1];
    const float* bq = (const float*)d_in[2];
    const float* Wk = (const float*)d_in[3];
    const float* bk = (const float*)d_in[4];
    const float* Wv = (const float*)d_in[5];
    const float* bv = (const float*)d_in[6];
    const float* Wo = (const float*)d_in[7];
    const float* bo = (const float*)d_in[8];
    float* out = (float*)d_out;

    cudaFuncSetAttribute(qkv_fp16_kernel,
                         cudaFuncAttributeMaxDynamicSharedMemorySize, QKV_SMEM);
    cudaFuncSetAttribute(flash_fp16_kernel,
                         cudaFuncAttributeMaxDynamicSharedMemorySize, F_SMEM);
    cudaFuncSetAttribute(out_fp16_kernel,
                         cudaFuncAttributeMaxDynamicSharedMemorySize, O_SMEM);

    prepass_kernel<<<5632, 256>>>(x, Wq, Wk, Wv, Wo);

    dim3 g1(Mc / 128, Hc);
    qkv_fp16_kernel<<<g1, 256, QKV_SMEM>>>(bq, bk, bv);

    dim3 g2(Sc / 128, Bc * Hc);
    flash_fp16_kernel<<<g2, 256, F_SMEM>>>();

    dim3 g3(Ec / 128, Mc / 128);
    out_fp16_kernel<<<g3, 256, O_SMEM>>>(bo, out);
}